// round 15
// baseline (speedup 1.0000x reference)
#include <cuda_runtime.h>
#include <cuda_fp16.h>

#define Bz 8
#define Lz 512
#define Dz 128
#define D2 64   // Dz/2 half2 pairs

// ---- scratch (device globals; no allocation allowed) ----
__device__ __half2 g_Qh[Bz*Lz*D2];
__device__ __half2 g_Kh[Bz*Lz*D2];
__device__ float   g_V [Bz*Lz*Dz];
__device__ __half2 g_w2h[D2];        // combined score weights (half2)
__device__ float   g_b[1];

__device__ __forceinline__ void cp16(unsigned smem, const void* g){
    asm volatile("cp.async.ca.shared.global [%0], [%1], 16;" :: "r"(smem), "l"(g));
}

// ---- projection tile body: Out[n,o] = sum_i X[n,i]*W[o,i] + b[o] ----
// 64n x 64o tile, 256 thr, thread = 4n x 4o. K split in two 64-halves.
// which: 0 -> g_Qh (half2), 1 -> g_Kh (half2), 2 -> g_V (fp32)
__device__ __forceinline__ void proj_tile(
        const float* __restrict__ X, const float* __restrict__ W,
        const float* __restrict__ bias, int which, int n0, int o0,
        float* Ws, float* Xs, int tid){
    int tr = tid >> 4;
    int tc = tid & 15;

    float acc[4][4];
    #pragma unroll
    for (int r = 0; r < 4; r++)
        #pragma unroll
        for (int j = 0; j < 4; j++) acc[r][j] = 0.f;

    #pragma unroll
    for (int kh = 0; kh < 2; kh++){
        __syncthreads();
        for (int idx = tid; idx < 1024; idx += 256){
            int r = idx >> 4, c = idx & 15;
            *(float4*)&Ws[r*68 + c*4] = *(const float4*)&W[(o0+r)*Dz + kh*64 + c*4];
            *(float4*)&Xs[r*68 + c*4] = *(const float4*)&X[(n0+r)*Dz + kh*64 + c*4];
        }
        __syncthreads();
        #pragma unroll 4
        for (int c = 0; c < 16; c++){
            float4 w0 = *(float4*)&Ws[(2*tc   )*68 + c*4];
            float4 w1 = *(float4*)&Ws[(2*tc+ 1)*68 + c*4];
            float4 w2 = *(float4*)&Ws[(2*tc+32)*68 + c*4];
            float4 w3 = *(float4*)&Ws[(2*tc+33)*68 + c*4];
            #pragma unroll
            for (int r = 0; r < 4; r++){
                float4 x = *(float4*)&Xs[(4*tr+r)*68 + c*4];
                acc[r][0] += w0.x*x.x + w0.y*x.y + w0.z*x.z + w0.w*x.w;
                acc[r][1] += w1.x*x.x + w1.y*x.y + w1.z*x.z + w1.w*x.w;
                acc[r][2] += w2.x*x.x + w2.y*x.y + w2.z*x.z + w2.w*x.w;
                acc[r][3] += w3.x*x.x + w3.y*x.y + w3.z*x.z + w3.w*x.w;
            }
        }
    }

    float b0 = bias[o0 + 2*tc],      b1 = bias[o0 + 2*tc + 1];
    float b2 = bias[o0 + 2*tc + 32], b3 = bias[o0 + 2*tc + 33];

    if (which == 2){
        #pragma unroll
        for (int r = 0; r < 4; r++){
            int n = n0 + 4*tr + r;
            *(float2*)&g_V[n*Dz + o0 + 2*tc]      = make_float2(acc[r][0]+b0, acc[r][1]+b1);
            *(float2*)&g_V[n*Dz + o0 + 2*tc + 32] = make_float2(acc[r][2]+b2, acc[r][3]+b3);
        }
    } else {
        __half2* dst = which ? g_Kh : g_Qh;
        int d2a = (o0 >> 1) + tc;
        int d2b = d2a + 16;
        #pragma unroll
        for (int r = 0; r < 4; r++){
            int n = n0 + 4*tr + r;
            dst[n*D2 + d2a] = __floats2half2_rn(acc[r][0]+b0, acc[r][1]+b1);
            dst[n*D2 + d2b] = __floats2half2_rn(acc[r][2]+b2, acc[r][3]+b3);
        }
    }
}

// ---- launch 1: Q/K/V projections + prep (1-D grid 385) ----
__global__ void __launch_bounds__(256, 2)
k_proj_all(const float* __restrict__ Xq, const float* __restrict__ Xk,
           const float* __restrict__ Xv,
           const float* __restrict__ Wq, const float* __restrict__ bq,
           const float* __restrict__ Wk, const float* __restrict__ bk,
           const float* __restrict__ Wv, const float* __restrict__ bv,
           const float* wd, const float* bd, const float* ws,
           const float* bs, const float* wt, const float* bt){
    __shared__ __align__(16) float sm[2*64*68];
    int id = blockIdx.x;
    int tid = threadIdx.x;
    if (id == 384){
        if (tid < D2){
            float base = 0.08838834764831845f; // 1/sqrt(128)
            float wx = base + wd[2*tid]   + ws[2*tid]   + wt[2*tid];
            float wy = base + wd[2*tid+1] + ws[2*tid+1] + wt[2*tid+1];
            g_w2h[tid] = __floats2half2_rn(wx, wy);
        }
        if (tid == 0) g_b[0] = bd[0] + bs[0] + bt[0];
        return;
    }
    int which = id >> 7;                  // 0 = Q, 1 = K, 2 = V
    int rem = id & 127;
    int n0 = (rem & 63) * 64;
    int o0 = (rem >> 6) * 64;
    const float* X = (which==0) ? Xq : (which==1) ? Xk : Xv;
    const float* W = (which==0) ? Wq : (which==1) ? Wk : Wv;
    const float* bs_ = (which==0) ? bq : (which==1) ? bk : bv;
    proj_tile(X, W, bs_, which, n0, o0, sm, sm + 64*68, tid);
}

// ---- launch 2: scores + softmax + AV, fully fused ----
// CTA = (16 q, b), 256 thr. Phase 1: warp w computes logits for q rows
// 2w,2w+1 (HFMA2 + tanh.f16x2, K tiles in smem), softmax in registers,
// attn -> fp16 smem. Phase 2: AV with V double-buffered via cp.async;
// warp reads only its own 2 attn rows (broadcast LDS).
__global__ void __launch_bounds__(256, 2)
k_scores_av(float* __restrict__ Out){
    __shared__ __align__(16) char smb[49152];   // 48KB union
    // phase 1: Ksh [D2][64] h2 @0 (16KB), Qsh [16][D2] h2 @16K (4KB), swh @20K
    // phase 2: Vs[2][32][128] f32 @0 (32KB), aPh [16][512] half @32K (16KB)
    __half2* Ksh = (__half2*)smb;
    __half2* Qsh = (__half2*)(smb + 16384);
    __half2* swh = (__half2*)(smb + 20480);
    __half*  aPh = (__half*)(smb + 32768);
    float*   Vs0 = (float*)smb;
    float*   Vs1 = (float*)(smb + 16384);

    int id  = blockIdx.x;
    int b   = id >> 5;
    int q0  = (id & 31) * 16;
    int tid = threadIdx.x;
    int kl  = tid & 31, w = tid >> 5;

    for (int idx = tid; idx < 16*D2; idx += 256){
        int q = idx >> 6, d2 = idx & 63;
        Qsh[q*D2 + d2] = g_Qh[(b*Lz + q0 + q)*D2 + d2];
    }
    if (tid < D2) swh[tid] = g_w2h[tid];
    float ball = g_b[0];

    const __half2* Kg = &g_Kh[(b*Lz)*D2];
    int frow = tid >> 4, fc4 = tid & 15;

    float4 pre[4];
    #pragma unroll
    for (int i = 0; i < 4; i++)
        pre[i] = *(const float4*)&Kg[(frow + i*16)*D2 + fc4*4];

    float va[16], vb[16];

    #pragma unroll
    for (int kt = 0; kt < 8; kt++){
        __syncthreads();
        #pragma unroll
        for (int i = 0; i < 4; i++){
            int r = frow + i*16;
            const __half2* h = (const __half2*)&pre[i];
            #pragma unroll
            for (int j = 0; j < 4; j++){
                int d2 = fc4*4 + j;
                Ksh[d2*64 + (r ^ d2)] = h[j];
            }
        }
        __syncthreads();
        if (kt < 7){
            #pragma unroll
            for (int i = 0; i < 4; i++)
                pre[i] = *(const float4*)&Kg[((kt+1)*64 + frow + i*16)*D2 + fc4*4];
        }

        float fa0 = 0.f, fb0 = 0.f, fa1 = 0.f, fb1 = 0.f;
        #pragma unroll
        for (int g = 0; g < 8; g++){
            __half2 z = __floats2half2_rn(0.f, 0.f);
            __half2 ha0 = z, hb0 = z, ha1 = z, hb1 = z;
            #pragma unroll
            for (int u = 0; u < 8; u++){
                int d2 = g*8 + u;
                __half2 qa = Qsh[(2*w  )*D2 + d2];
                __half2 qb = Qsh[(2*w+1)*D2 + d2];
                __half2 w2 = swh[d2];
                __half2 ka = Ksh[d2*64 + (kl ^ d2)];
                __half2 kb = Ksh[d2*64 + ((kl + 32) ^ d2)];
                __half2 s0 = __hadd2(qa, ka);
                __half2 s1 = __hadd2(qa, kb);
                __half2 s2 = __hadd2(qb, ka);
                __half2 s3 = __hadd2(qb, kb);
                unsigned t0, t1, t2, t3;
                asm("tanh.approx.f16x2 %0, %1;" : "=r"(t0) : "r"(*(unsigned*)&s0));
                asm("tanh.approx.f16x2 %0, %1;" : "=r"(t1) : "r"(*(unsigned*)&s1));
                asm("tanh.approx.f16x2 %0, %1;" : "=r"(t2) : "r"(*(unsigned*)&s2));
                asm("tanh.approx.f16x2 %0, %1;" : "=r"(t3) : "r"(*(unsigned*)&s3));
                ha0 = __hfma2(w2, *(__half2*)&t0, ha0);
                hb0 = __hfma2(w2, *(__half2*)&t1, hb0);
                ha1 = __hfma2(w2, *(__half2*)&t2, ha1);
                hb1 = __hfma2(w2, *(__half2*)&t3, hb1);
            }
            float2 x0 = __half22float2(ha0);
            float2 x1 = __half22float2(hb0);
            float2 x2 = __half22float2(ha1);
            float2 x3 = __half22float2(hb1);
            fa0 += x0.x + x0.y;
            fb0 += x1.x + x1.y;
            fa1 += x2.x + x2.y;
            fb1 += x3.x + x3.y;
        }
        va[2*kt] = fa0 + ball; va[2*kt+1] = fb0 + ball;
        vb[2*kt] = fa1 + ball; vb[2*kt+1] = fb1 + ball;
    }

    // softmax (rows 2w, 2w+1) from registers
    float ma = -1e30f, mb = -1e30f;
    #pragma unroll
    for (int j = 0; j < 16; j++){ ma = fmaxf(ma, va[j]); mb = fmaxf(mb, vb[j]); }
    #pragma unroll
    for (int s = 16; s; s >>= 1){
        ma = fmaxf(ma, __shfl_xor_sync(~0u, ma, s));
        mb = fmaxf(mb, __shfl_xor_sync(~0u, mb, s));
    }
    float sa = 0.f, sb = 0.f;
    #pragma unroll
    for (int j = 0; j < 16; j++){
        va[j] = __expf(va[j] - ma); sa += va[j];
        vb[j] = __expf(vb[j] - mb); sb += vb[j];
    }
    #pragma unroll
    for (int s = 16; s; s >>= 1){
        sa += __shfl_xor_sync(~0u, sa, s);
        sb += __shfl_xor_sync(~0u, sb, s);
    }
    float ia = 1.f / sa, ib = 1.f / sb;

    // attn -> fp16 smem (region disjoint from Ksh/Qsh; same-warp reads later)
    __half* ra = &aPh[(2*w    )*Lz];
    __half* rb = &aPh[(2*w + 1)*Lz];
    #pragma unroll
    for (int kt = 0; kt < 8; kt++){
        ra[kt*64 + kl]      = __float2half(va[2*kt]   * ia);
        ra[kt*64 + 32 + kl] = __float2half(va[2*kt+1] * ia);
        rb[kt*64 + kl]      = __float2half(vb[2*kt]   * ib);
        rb[kt*64 + 32 + kl] = __float2half(vb[2*kt+1] * ib);
    }

    // ---- phase 2: AV ----
    __syncthreads();   // everyone done with Ksh/Qsh before Vs overwrites

    const float* Vg = &g_V[(b*Lz)*Dz];
    int vrow = tid >> 5;                 // +i*8
    int vc4  = (tid & 31) * 4;
    unsigned sv0 = (unsigned)__cvta_generic_to_shared(Vs0) + tid*16u;
    unsigned sv1 = (unsigned)__cvta_generic_to_shared(Vs1) + tid*16u;

    {
        #pragma unroll
        for (int i = 0; i < 4; i++)
            cp16(sv0 + i*4096u, &Vg[(vrow + i*8)*Dz + vc4]);
        asm volatile("cp.async.commit_group;");
    }

    float4 acc0 = make_float4(0.f,0.f,0.f,0.f);
    float4 acc1 = acc0;
    const __half* pa = &aPh[(2*w    )*Lz];
    const __half* pb = &aPh[(2*w + 1)*Lz];

    for (int kt = 0; kt < 16; kt++){
        int buf = kt & 1;
        if (kt + 1 < 16){
            int k0n = (kt + 1) * 32;
            unsigned sv = buf ? sv0 : sv1;
            #pragma unroll
            for (int i = 0; i < 4; i++)
                cp16(sv + i*4096u, &Vg[(k0n + vrow + i*8)*Dz + vc4]);
            asm volatile("cp.async.commit_group;");
            asm volatile("cp.async.wait_group 1;");
        } else {
            asm volatile("cp.async.wait_group 0;");
        }
        __syncthreads();

        const float* Vt = buf ? Vs1 : Vs0;
        int k0 = kt * 32;
        #pragma unroll 8
        for (int j = 0; j < 32; j++){
            float4 v = *(const float4*)&Vt[j*Dz + (tid & 31)*4];
            float p0 = __half2float(pa[k0 + j]);
            float p1 = __half2float(pb[k0 + j]);
            acc0.x += p0*v.x; acc0.y += p0*v.y; acc0.z += p0*v.z; acc0.w += p0*v.w;
            acc1.x += p1*v.x; acc1.y += p1*v.y; acc1.z += p1*v.z; acc1.w += p1*v.w;
        }
        __syncthreads();
    }
    *(float4*)&Out[(b*Lz + q0 + 2*w    )*Dz + (tid & 31)*4] = acc0;
    *(float4*)&Out[(b*Lz + q0 + 2*w + 1)*Dz + (tid & 31)*4] = acc1;
}

extern "C" void kernel_launch(void* const* d_in, const int* in_sizes, int n_in,
                              void* d_out, int out_size){
    const float* query = (const float*)d_in[0];
    const float* key_  = (const float*)d_in[1];
    const float* value = (const float*)d_in[2];
    const float* Wq = (const float*)d_in[3];
    const float* bq = (const float*)d_in[4];
    const float* Wk = (const float*)d_in[5];
    const float* bk = (const float*)d_in[6];
    const float* Wv = (const float*)d_in[7];
    const float* bv = (const float*)d_in[8];
    const float* wd = (const float*)d_in[9];
    const float* bd = (const float*)d_in[10];
    const float* ws = (const float*)d_in[11];
    const float* bs = (const float*)d_in[12];
    const float* wt = (const float*)d_in[13];
    const float* bt = (const float*)d_in[14];
    float* out = (float*)d_out;

    k_proj_all<<<385, 256>>>(query, key_, value, Wq, bq, Wk, bk, Wv, bv,
                             wd, bd, ws, bs, wt, bt);
    k_scores_av<<<256, 256>>>(out);
}